// round 9
// baseline (speedup 1.0000x reference)
#include <cuda_runtime.h>
#include <cstdint>

// out[row, :] = features[rules[row], :]
// features: [N_ACTIVE=200000, C=64] fp32   (51.2 MB — resident in 126 MB L2)
// rules:    [N_ROWS=524288] int32 (2 MB — L2 resident)
// out:      [N_ROWS, 64] fp32
//
// R7 -> R8: revert ILP=8 (occupancy loss killed it). Keep ILP=4 @ 32 regs,
// but switch from strided to CONTIGUOUS quarter-row per thread:
//   - one rules load per thread (was 4) -> 75% fewer index LDGs + shorter dep chain
//   - thread's 4 gathers hit one 64B segment; 4 threads cover a 256B row
//   - stores stay fully coalesced (warp = 2KB contiguous), __stcs retained

__global__ void __launch_bounds__(256)
bl_gather_kernel(const float4* __restrict__ feat,
                 const int* __restrict__ rules,
                 float4* __restrict__ out,
                 int n_rows)
{
    // each thread: one quarter-row = 4 consecutive float4s
    const int tid  = blockIdx.x * blockDim.x + threadIdx.x;
    const int row  = tid >> 2;          // 4 threads per row
    const int q    = (tid & 3) * 4;     // starting float4 within the row

    if (row >= n_rows) return;

    const int r = __ldg(&rules[row]);   // single index load per thread
    const float4* src = feat + (long long)r * 16 + q;

    // 4 independent 128-bit gathers (one 64B segment)
    float4 v0 = __ldg(src + 0);
    float4 v1 = __ldg(src + 1);
    float4 v2 = __ldg(src + 2);
    float4 v3 = __ldg(src + 3);

    float4* dst = out + (long long)row * 16 + q;
    __stcs(dst + 0, v0);
    __stcs(dst + 1, v1);
    __stcs(dst + 2, v2);
    __stcs(dst + 3, v3);
}

extern "C" void kernel_launch(void* const* d_in, const int* in_sizes, int n_in,
                              void* d_out, int out_size)
{
    const float4* feat  = (const float4*)d_in[0];   // features [nActive, 64] fp32
    const int*    rules = (const int*)d_in[1];      // rules [n_rows] int32

    int n_rows = in_sizes[1];                       // 524288
    float4* out = (float4*)d_out;

    const int threads = 256;
    int total_threads = n_rows * 4;                 // 4 threads per row
    int blocks = (total_threads + threads - 1) / threads;   // 8192
    bl_gather_kernel<<<blocks, threads>>>(feat, rules, out, n_rows);
}

// round 12
// speedup vs baseline: 1.0965x; 1.0965x over previous
#include <cuda_runtime.h>
#include <cstdint>

// out[row, :] = features[rules[row], :]
// features: [N_ACTIVE=200000, C=64] fp32   (51.2 MB — resident in 126 MB L2)
// rules:    [N_ROWS=524288] int32 (2 MB)
// out:      [N_ROWS, 64] fp32
//
// R9 -> R10: revert quarter-row layout (4x L1tex wavefront inflation per LDG).
// Back to R4's strided-coalesced ILP=4 body, now PERSISTENT single-wave:
//   - grid = 148 SMs x 8 CTAs = 1184 blocks, grid-stride loop (~7 iters)
//   - avoids per-wave cross-CTA L1tex-queue spread + wave transitions
//     (B300 spr_max ~2x at occ=8 with front-batched LDG.128, 7 waves in R4)
//   - __launch_bounds__(256,8) pins regs <=32 for full residency
//   - __stcs stores keep the feature table L2-resident (verified R4)

#define ILP 4

__global__ void __launch_bounds__(256, 8)
bl_gather_kernel(const float4* __restrict__ feat,
                 const int* __restrict__ rules,
                 float4* __restrict__ out,
                 int total_vec4)  // n_rows * 16
{
    const int nth  = gridDim.x * blockDim.x;     // total threads
    const int step = nth * ILP;
    int base = blockIdx.x * blockDim.x + threadIdx.x;

    for (; base < total_vec4; base += step) {
        int    idx[ILP];
        int    r[ILP];
        float4 v[ILP];

        // index loads: coalesced + broadcast within 16-thread groups
        #pragma unroll
        for (int i = 0; i < ILP; i++) {
            idx[i] = base + i * nth;
            int row = idx[i] >> 4;
            r[i] = (idx[i] < total_vec4) ? __ldg(&rules[row]) : 0;
        }
        // gather phase: 4 independent 128-bit loads in flight per thread,
        // 16 consecutive lanes share a row -> 4 lines per warp LDG
        #pragma unroll
        for (int i = 0; i < ILP; i++) {
            int c4 = idx[i] & 15;
            if (idx[i] < total_vec4)
                v[i] = __ldg(&feat[(long long)r[i] * 16 + c4]);
        }
        // store phase: streaming (evict-first) protects feature L2 residency
        #pragma unroll
        for (int i = 0; i < ILP; i++) {
            if (idx[i] < total_vec4)
                __stcs(&out[idx[i]], v[i]);
        }
    }
}

extern "C" void kernel_launch(void* const* d_in, const int* in_sizes, int n_in,
                              void* d_out, int out_size)
{
    const float4* feat  = (const float4*)d_in[0];   // features [nActive, 64] fp32
    const int*    rules = (const int*)d_in[1];      // rules [n_rows] int32

    int n_rows     = in_sizes[1];          // 524288
    int total_vec4 = n_rows * 16;          // 8,388,608

    float4* out = (float4*)d_out;

    const int threads = 256;
    const int blocks  = 148 * 8;           // one persistent wave (full residency)
    bl_gather_kernel<<<blocks, threads>>>(feat, rules, out, total_vec4);
}

// round 13
// speedup vs baseline: 1.2883x; 1.1750x over previous
#include <cuda_runtime.h>
#include <cstdint>

// out[row, :] = features[rules[row], :]
// features: [N_ACTIVE=200000, C=64] fp32   (51.2 MB — resident in 126 MB L2)
// rules:    [N_ROWS=524288] int32
// out:      [N_ROWS, 64] fp32
//
// R12 -> R13: revert persistent loop (loop-carried LSU serialization regressed).
// Back to R4's exit-after-work multi-wave shape, upgraded to Blackwell 256-bit
// vector memory ops (sm_100a+):
//   - each thread moves 2 x 32B (float8) instead of 4 x 16B: same bytes in
//     flight, HALF the LSU instructions (2 LDG.256 + 2 STG.256 vs 4+4+idx)
//   - 8 lanes share a gathered row -> warp LDG.256 = 8 x 128B lines (optimal wf)
//   - st.global.cs (evict-first) retained: keeps feature table L2-resident
//     (verified in R4: DRAM traffic == output write stream only)

#define ILP 2  // two float8 per thread, grid-strided

__device__ __forceinline__ void ldg256(const float* a, float* v) {
    asm volatile("ld.global.nc.v8.f32 {%0,%1,%2,%3,%4,%5,%6,%7}, [%8];"
                 : "=f"(v[0]), "=f"(v[1]), "=f"(v[2]), "=f"(v[3]),
                   "=f"(v[4]), "=f"(v[5]), "=f"(v[6]), "=f"(v[7])
                 : "l"(a));
}
__device__ __forceinline__ void stg256_cs(float* a, const float* v) {
    asm volatile("st.global.cs.v8.f32 [%0], {%1,%2,%3,%4,%5,%6,%7,%8};"
                 :: "l"(a),
                    "f"(v[0]), "f"(v[1]), "f"(v[2]), "f"(v[3]),
                    "f"(v[4]), "f"(v[5]), "f"(v[6]), "f"(v[7])
                 : "memory");
}

__global__ void __launch_bounds__(256)
bl_gather_kernel(const float* __restrict__ feat,
                 const int* __restrict__ rules,
                 float* __restrict__ out,
                 int total_vec8)  // n_rows * 8
{
    const int tid = blockIdx.x * blockDim.x + threadIdx.x;
    const int nth = gridDim.x * blockDim.x;

    int idx[ILP];
    int r[ILP];
    float v[ILP][8];

    // index loads: 4 distinct rows per warp, broadcast within 8-lane groups
    #pragma unroll
    for (int i = 0; i < ILP; i++) {
        idx[i] = tid + i * nth;
        int row = idx[i] >> 3;              // 8 float8 per row
        r[i] = (idx[i] < total_vec8) ? __ldg(&rules[row]) : 0;
    }
    // gather: ILP independent 256-bit loads in flight
    #pragma unroll
    for (int i = 0; i < ILP; i++) {
        int c8 = idx[i] & 7;
        if (idx[i] < total_vec8)
            ldg256(feat + ((long long)r[i] * 64 + c8 * 8), v[i]);
    }
    // store: 256-bit streaming (evict-first) stores, fully coalesced
    #pragma unroll
    for (int i = 0; i < ILP; i++) {
        if (idx[i] < total_vec8)
            stg256_cs(out + (long long)idx[i] * 8, v[i]);
    }
}

extern "C" void kernel_launch(void* const* d_in, const int* in_sizes, int n_in,
                              void* d_out, int out_size)
{
    const float* feat  = (const float*)d_in[0];   // features [nActive, 64] fp32
    const int*   rules = (const int*)d_in[1];     // rules [n_rows] int32

    int n_rows     = in_sizes[1];          // 524288
    int total_vec8 = n_rows * 8;           // 4,194,304

    float* out = (float*)d_out;

    const int threads = 256;
    int blocks = (total_vec8 + threads * ILP - 1) / (threads * ILP);  // 8192
    bl_gather_kernel<<<blocks, threads>>>(feat, rules, out, total_vec8);
}